// round 3
// baseline (speedup 1.0000x reference)
#include <cuda_runtime.h>
#include <math.h>

#define NB 64
#define NT 128
#define NN 64     // nodes
#define NC 128    // channels
#define NH 64     // hidden
#define NE 192    // 3 gates * 64
#define PD 132    // dup-buffer pitch (floats): [feat][2*node], 16B-aligned rows, conflict-spread

typedef unsigned long long u64;

// Precomputed input-path gate contributions, opaque per-thread register dump:
// g_U[((bt*12)+q)*256 + tid], q = gate*4 + j, value = (acc[pair0], acc[pair1]). 384 MiB.
static __device__ ulonglong2 g_U[(size_t)NB * NT * 12 * 256];

__device__ __forceinline__ u64 ffma2(u64 a, u64 b, u64 c) {
    u64 d;
    asm("fma.rn.f32x2 %0, %1, %2, %3;" : "=l"(d) : "l"(a), "l"(b), "l"(c));
    return d;
}
__device__ __forceinline__ u64 pk(float lo, float hi) {
    u64 r; asm("mov.b64 %0, {%1, %2};" : "=l"(r) : "f"(lo), "f"(hi)); return r;
}
__device__ __forceinline__ void upk(u64 v, float& lo, float& hi) {
    asm("mov.b64 {%0, %1}, %2;" : "=f"(lo), "=f"(hi) : "l"(v));
}

// out = A @ P accumulate. P natural [node m][feat d] pitch 64 (sN),
// A dup [m][2n] pitch PD (sAd). acc[ip][j] = pair (out[n0+j][d0+2ip], out[n0+j][d0+2ip+1]).
__device__ __forceinline__ void mm2acc(u64 acc[2][4], const float* __restrict__ sN_,
                                       const float* __restrict__ sAd_, int n0, int d0)
{
#pragma unroll
    for (int ip = 0; ip < 2; ip++)
#pragma unroll
        for (int j = 0; j < 4; j++) acc[ip][j] = 0ull;
#pragma unroll 2
    for (int m = 0; m < 64; m++) {
        ulonglong2 p   = *(const ulonglong2*)&sN_[m * 64 + d0];
        ulonglong2 a01 = *(const ulonglong2*)&sAd_[m * PD + 2 * n0];
        ulonglong2 a23 = *(const ulonglong2*)&sAd_[m * PD + 2 * n0 + 4];
        acc[0][0] = ffma2(p.x, a01.x, acc[0][0]);  acc[1][0] = ffma2(p.y, a01.x, acc[1][0]);
        acc[0][1] = ffma2(p.x, a01.y, acc[0][1]);  acc[1][1] = ffma2(p.y, a01.y, acc[1][1]);
        acc[0][2] = ffma2(p.x, a23.x, acc[0][2]);  acc[1][2] = ffma2(p.y, a23.x, acc[1][2]);
        acc[0][3] = ffma2(p.x, a23.y, acc[0][3]);  acc[1][3] = ffma2(p.y, a23.y, acc[1][3]);
    }
}

// Fused 3-gate accumulate for one hop: G += x_k @ W_k (x dup [feat m][2n] pitch PD,
// W natural [m][192] with gate offsets 0/64/128; pairs along e).
__device__ __forceinline__ void gate3acc(u64 af[2][4], u64 ag[2][4], u64 ac[2][4],
                                         const float* __restrict__ xD,
                                         const float* __restrict__ wb, int n0, int d0)
{
#pragma unroll 2
    for (int m = 0; m < 64; m++) {
        ulonglong2 x01 = *(const ulonglong2*)&xD[m * PD + 2 * n0];
        ulonglong2 x23 = *(const ulonglong2*)&xD[m * PD + 2 * n0 + 4];
        ulonglong2 wf  = *(const ulonglong2*)&wb[m * NE + d0];
        ulonglong2 wg  = *(const ulonglong2*)&wb[m * NE + 64 + d0];
        ulonglong2 wc  = *(const ulonglong2*)&wb[m * NE + 128 + d0];
        af[0][0] = ffma2(wf.x, x01.x, af[0][0]);  af[1][0] = ffma2(wf.y, x01.x, af[1][0]);
        af[0][1] = ffma2(wf.x, x01.y, af[0][1]);  af[1][1] = ffma2(wf.y, x01.y, af[1][1]);
        af[0][2] = ffma2(wf.x, x23.x, af[0][2]);  af[1][2] = ffma2(wf.y, x23.x, af[1][2]);
        af[0][3] = ffma2(wf.x, x23.y, af[0][3]);  af[1][3] = ffma2(wf.y, x23.y, af[1][3]);
        ag[0][0] = ffma2(wg.x, x01.x, ag[0][0]);  ag[1][0] = ffma2(wg.y, x01.x, ag[1][0]);
        ag[0][1] = ffma2(wg.x, x01.y, ag[0][1]);  ag[1][1] = ffma2(wg.y, x01.y, ag[1][1]);
        ag[0][2] = ffma2(wg.x, x23.x, ag[0][2]);  ag[1][2] = ffma2(wg.y, x23.x, ag[1][2]);
        ag[0][3] = ffma2(wg.x, x23.y, ag[0][3]);  ag[1][3] = ffma2(wg.y, x23.y, ag[1][3]);
        ac[0][0] = ffma2(wc.x, x01.x, ac[0][0]);  ac[1][0] = ffma2(wc.y, x01.x, ac[1][0]);
        ac[0][1] = ffma2(wc.x, x01.y, ac[0][1]);  ac[1][1] = ffma2(wc.y, x01.y, ac[1][1]);
        ac[0][2] = ffma2(wc.x, x23.x, ac[0][2]);  ac[1][2] = ffma2(wc.y, x23.x, ac[1][2]);
        ac[0][3] = ffma2(wc.x, x23.y, ac[0][3]);  ac[1][3] = ffma2(wc.y, x23.y, ac[1][3]);
    }
}

__device__ __forceinline__ void unpack44(const u64 a2[2][4], float v[4][4]) {
#pragma unroll
    for (int j = 0; j < 4; j++) {
        upk(a2[0][j], v[0][j], v[1][j]);
        upk(a2[1][j], v[2][j], v[3][j]);
    }
}

// Store v[i=d][j=n] tile into natural sN [n][d] (pitch 64) and dup sD [d][2n] (pitch PD).
__device__ __forceinline__ void store_ND(const float v[4][4], float* sN_, float* sD_,
                                         int n0, int d0)
{
#pragma unroll
    for (int j = 0; j < 4; j++)
        *(float4*)&sN_[(n0 + j) * 64 + d0] = make_float4(v[0][j], v[1][j], v[2][j], v[3][j]);
#pragma unroll
    for (int i = 0; i < 4; i++) {
        *(float4*)&sD_[(d0 + i) * PD + 2 * n0]     = make_float4(v[i][0], v[i][0], v[i][1], v[i][1]);
        *(float4*)&sD_[(d0 + i) * PD + 2 * n0 + 4] = make_float4(v[i][2], v[i][2], v[i][3], v[i][3]);
    }
}
__device__ __forceinline__ void storeD(const float v[4][4], float* sD_, int n0, int d0) {
#pragma unroll
    for (int i = 0; i < 4; i++) {
        *(float4*)&sD_[(d0 + i) * PD + 2 * n0]     = make_float4(v[i][0], v[i][0], v[i][1], v[i][1]);
        *(float4*)&sD_[(d0 + i) * PD + 2 * n0 + 4] = make_float4(v[i][2], v[i][2], v[i][3], v[i][3]);
    }
}

// ---------------------------------------------------------------------------
// Phase 1: per (b,t) tile. grid = 8192, block = 256. smem = 182272 B.
// ---------------------------------------------------------------------------
__global__ void __launch_bounds__(256, 1) phase1_kernel(
    const float* __restrict__ frames, const float* __restrict__ adj,
    const float* __restrict__ encW, const float* __restrict__ encB,
    const float* __restrict__ Wfu, const float* __restrict__ Wgu, const float* __restrict__ Wcu,
    const float* __restrict__ bf, const float* __restrict__ bg, const float* __restrict__ bc)
{
    extern __shared__ float sm[];
    float* sFrD = sm;              // [c][2n] dup, pitch 128: 16384
    float* sEW  = sm + 16384;      // [c][d] natural: 8192
    float* sWu  = sm;              // later: [m][192]: 12288 (overlays sFrD)
    float* sAd  = sm + 24576;      // [m][2n] dup, pitch PD: 8448
    float* sD   = sm + 33024;      // dup intermediate: 8448
    float* sN   = sm + 41472;      // natural intermediate [n][d] pitch 64: 4096

    const int tid = threadIdx.x;
    const int bt = blockIdx.x;
    const float* fr = frames + (size_t)bt * (NC * NN);
    const float* Ap = adj + (size_t)bt * (NN * NN);

    // Stage frames dup [c][2n]
    for (int i = tid; i < NC * NN; i += 256) {
        int c = i >> 6, n = i & 63;
        float v = fr[i];
        sFrD[c * 128 + 2 * n] = v;
        sFrD[c * 128 + 2 * n + 1] = v;
    }
    // encW natural
    for (int i = tid; i < (NC * NH) / 4; i += 256)
        ((float4*)sEW)[i] = ((const float4*)encW)[i];
    // adjacency dup [m][2n] : Ad[m][2n] = A[n][m]
    for (int i = tid; i < NN * NN; i += 256) {
        int n = i >> 6, m = i & 63;
        float v = Ap[i];
        sAd[m * PD + 2 * n] = v;
        sAd[m * PD + 2 * n + 1] = v;
    }
    __syncthreads();

    const int n0 = (tid & 15) * 4;
    const int d0 = (tid >> 4) * 4;

    // Encode: x[n][d] = sum_c fr[c][n] * encW[c][d] + encB[d]  (pairs along d)
    u64 xa[2][4];
    {
        float4 eb = *(const float4*)&encB[d0];
        u64 b01 = pk(eb.x, eb.y), b23 = pk(eb.z, eb.w);
#pragma unroll
        for (int j = 0; j < 4; j++) { xa[0][j] = b01; xa[1][j] = b23; }
#pragma unroll 2
        for (int c = 0; c < NC; c++) {
            ulonglong2 f01 = *(const ulonglong2*)&sFrD[c * 128 + 2 * n0];
            ulonglong2 f23 = *(const ulonglong2*)&sFrD[c * 128 + 2 * n0 + 4];
            ulonglong2 w   = *(const ulonglong2*)&sEW[c * 64 + d0];
            xa[0][0] = ffma2(w.x, f01.x, xa[0][0]);  xa[1][0] = ffma2(w.y, f01.x, xa[1][0]);
            xa[0][1] = ffma2(w.x, f01.y, xa[0][1]);  xa[1][1] = ffma2(w.y, f01.y, xa[1][1]);
            xa[0][2] = ffma2(w.x, f23.x, xa[0][2]);  xa[1][2] = ffma2(w.y, f23.x, xa[1][2]);
            xa[0][3] = ffma2(w.x, f23.y, xa[0][3]);  xa[1][3] = ffma2(w.y, f23.y, xa[1][3]);
        }
    }
    __syncthreads();   // all reads of sFrD/sEW done before sWu overlays them

    {
        float v[4][4];
        unpack44(xa, v);
        store_ND(v, sN, sD, n0, d0);
    }
    // Stage Wu hop 0
    for (int i = tid; i < 4096; i += 256) {
        int m = i >> 6, e = i & 63;
        sWu[m * NE + e]       = Wfu[i];
        sWu[m * NE + 64 + e]  = Wgu[i];
        sWu[m * NE + 128 + e] = Wcu[i];
    }
    __syncthreads();

    // Gate accumulators, init = biases
    u64 af[2][4], ag[2][4], ac[2][4];
    {
        float4 b4f = *(const float4*)&bf[d0];
        float4 b4g = *(const float4*)&bg[d0];
        float4 b4c = *(const float4*)&bc[d0];
        u64 f01 = pk(b4f.x, b4f.y), f23 = pk(b4f.z, b4f.w);
        u64 g01 = pk(b4g.x, b4g.y), g23 = pk(b4g.z, b4g.w);
        u64 c01 = pk(b4c.x, b4c.y), c23 = pk(b4c.z, b4c.w);
#pragma unroll
        for (int j = 0; j < 4; j++) {
            af[0][j] = f01; af[1][j] = f23;
            ag[0][j] = g01; ag[1][j] = g23;
            ac[0][j] = c01; ac[1][j] = c23;
        }
    }

    u64 mmacc[2][4];
    // hop 0 gates + y1 = A x
    gate3acc(af, ag, ac, sD, sWu, n0, d0);
    mm2acc(mmacc, sN, sAd, n0, d0);
    __syncthreads();
    {
        float v[4][4];
        unpack44(mmacc, v);
        store_ND(v, sN, sD, n0, d0);   // y1
    }
    for (int i = tid; i < 4096; i += 256) {
        int m = i >> 6, e = i & 63;
        sWu[m * NE + e]       = Wfu[4096 + i];
        sWu[m * NE + 64 + e]  = Wgu[4096 + i];
        sWu[m * NE + 128 + e] = Wcu[4096 + i];
    }
    __syncthreads();

    // hop 1 gates + y2 = A y1
    gate3acc(af, ag, ac, sD, sWu, n0, d0);
    mm2acc(mmacc, sN, sAd, n0, d0);
    __syncthreads();
    {
        float v[4][4];
        unpack44(mmacc, v);
        storeD(v, sD, n0, d0);         // y2 (dup only)
    }
    for (int i = tid; i < 4096; i += 256) {
        int m = i >> 6, e = i & 63;
        sWu[m * NE + e]       = Wfu[8192 + i];
        sWu[m * NE + 64 + e]  = Wgu[8192 + i];
        sWu[m * NE + 128 + e] = Wcu[8192 + i];
    }
    __syncthreads();

    // hop 2 gates
    gate3acc(af, ag, ac, sD, sWu, n0, d0);

    // Store U (coalesced register dump)
    ulonglong2* Ub = g_U + (size_t)bt * 12 * 256;
#pragma unroll
    for (int j = 0; j < 4; j++) {
        Ub[(0 * 4 + j) * 256 + tid] = make_ulonglong2(af[0][j], af[1][j]);
        Ub[(1 * 4 + j) * 256 + tid] = make_ulonglong2(ag[0][j], ag[1][j]);
        Ub[(2 * 4 + j) * 256 + tid] = make_ulonglong2(ac[0][j], ac[1][j]);
    }
}

// ---------------------------------------------------------------------------
// Phase 2: persistent recurrence. grid = 64, block = 256. smem = 231424 B.
// ---------------------------------------------------------------------------
__global__ void __launch_bounds__(256, 1) phase2_kernel(
    const float* __restrict__ adj, const float* __restrict__ h0,
    const float* __restrict__ Wfh, const float* __restrict__ Wgh, const float* __restrict__ Wch,
    const float* __restrict__ dW1, const float* __restrict__ db1,
    const float* __restrict__ dW2, const float* __restrict__ db2,
    const float* __restrict__ dW3, const float* __restrict__ db3,
    const float* __restrict__ osc, const float* __restrict__ obi,
    float* __restrict__ out)
{
    extern __shared__ float sm[];
    float* sWh = sm;               // [k*64+m][192]: 36864
    float* sAd = sm + 36864;       // [m][2n] dup: 8448
    float* sD  = sm + 45312;       // dup intermediate: 8448
    float* sN  = sm + 53760;       // natural [n][d]: 4096
    // decoder scratch overlays sAd (dead between mm2 and next staging)
    float* sPool = sAd;            // 64
    float* sZ1   = sAd + 64;       // 128
    float* sZ2   = sAd + 192;      // 64

    const int tid = threadIdx.x;
    const int b = blockIdx.x;

    // Stage hidden-path weights once
    for (int i = tid; i < 3 * 4096; i += 256) {
        int k = i >> 12; int r = i & 4095; int m = r >> 6; int e = r & 63;
        sWh[(k * 64 + m) * NE + e]       = Wfh[i];
        sWh[(k * 64 + m) * NE + 64 + e]  = Wgh[i];
        sWh[(k * 64 + m) * NE + 128 + e] = Wch[i];
    }
    // h0: natural + dup
    for (int i = tid; i < 4096; i += 256) {
        int n = i >> 6, d = i & 63;
        float v = h0[b * 4096 + i];
        sN[n * 64 + d] = v;
        sD[d * PD + 2 * n] = v;
        sD[d * PD + 2 * n + 1] = v;
    }
    __syncthreads();

    const int n0 = (tid & 15) * 4;
    const int d0 = (tid >> 4) * 4;

    for (int t = 0; t < NT; t++) {
        // Stage adjacency dup (overwrites decoder scratch — prev step sync'd)
        const float* Ap = adj + ((size_t)(b * NT + t)) * 4096;
        for (int i = tid; i < 4096; i += 256) {
            int n = i >> 6, m = i & 63;
            float v = Ap[i];
            sAd[m * PD + 2 * n] = v;
            sAd[m * PD + 2 * n + 1] = v;
        }
        // Init gate accs from U (gmem, independent of smem staging)
        u64 af[2][4], ag[2][4], ac[2][4];
        {
            const ulonglong2* Ub = g_U + ((size_t)(b * NT + t)) * 12 * 256;
#pragma unroll
            for (int j = 0; j < 4; j++) {
                ulonglong2 uf = Ub[(0 * 4 + j) * 256 + tid];
                ulonglong2 ug = Ub[(1 * 4 + j) * 256 + tid];
                ulonglong2 uc = Ub[(2 * 4 + j) * 256 + tid];
                af[0][j] = uf.x; af[1][j] = uf.y;
                ag[0][j] = ug.x; ag[1][j] = ug.y;
                ac[0][j] = uc.x; ac[1][j] = uc.y;
            }
        }
        __syncthreads();

        u64 mmacc[2][4];
        // hop 0 (h) + h1 = A h
        gate3acc(af, ag, ac, sD, sWh, n0, d0);
        mm2acc(mmacc, sN, sAd, n0, d0);
        __syncthreads();
        {
            float v[4][4];
            unpack44(mmacc, v);
            store_ND(v, sN, sD, n0, d0);    // h1
        }
        __syncthreads();

        // hop 1 (h1) + h2 = A h1
        gate3acc(af, ag, ac, sD, sWh + 64 * NE, n0, d0);
        mm2acc(mmacc, sN, sAd, n0, d0);
        __syncthreads();
        {
            float v[4][4];
            unpack44(mmacc, v);
            storeD(v, sD, n0, d0);          // h2 (dup only)
        }
        __syncthreads();

        // hop 2 (h2)
        gate3acc(af, ag, ac, sD, sWh + 128 * NE, n0, d0);

        // Nonlinearity -> h_new
        float hv[4][4];
        {
            float vf[4][4], vg[4][4], vc[4][4];
            unpack44(af, vf); unpack44(ag, vg); unpack44(ac, vc);
#pragma unroll
            for (int i = 0; i < 4; i++)
#pragma unroll
                for (int j = 0; j < 4; j++) {
                    float f = 1.0f / (1.0f + __expf(-vf[i][j]));
                    hv[i][j] = f * tanhf(vg[i][j]) + (1.0f - f) * tanhf(vc[i][j]);
                }
        }
        __syncthreads();   // all reads of sD(h2)/sN(h1) done
        store_ND(hv, sN, sD, n0, d0);       // h_new
        __syncthreads();

        // Decoder MLP
        if (tid < 64) {
            float s = 0.f;
            for (int n = 0; n < 64; n++) s += sN[n * 64 + tid];
            sPool[tid] = s * (1.0f / 64.0f);
        }
        __syncthreads();
        if (tid < 128) {
            float a = db1[tid];
            for (int d = 0; d < 64; d++) a += sPool[d] * dW1[d * 128 + tid];
            sZ1[tid] = fmaxf(a, 0.f);
        }
        __syncthreads();
        if (tid < 64) {
            float a = db2[tid];
            for (int i = 0; i < 128; i++) a += sZ1[i] * dW2[i * 64 + tid];
            sZ2[tid] = fmaxf(a, 0.f);
        }
        __syncthreads();
        if (tid < 6) {
            float a = db3[tid];
            for (int j = 0; j < 64; j++) a += sZ2[j] * dW3[j * 6 + tid];
            out[((size_t)(b * NT + t)) * 6 + tid] = a * osc[tid] + obi[tid];
        }
        __syncthreads();
    }

    // final_hidden[b,0,n,d] = sN (natural layout matches)
    float* fh = out + (size_t)NB * NT * 6 + (size_t)b * (NN * NH);
    for (int i = tid; i < 4096; i += 256)
        fh[i] = sN[i];
}

extern "C" void kernel_launch(void* const* d_in, const int* in_sizes, int n_in,
                              void* d_out, int out_size) {
    const float* frames = (const float*)d_in[0];
    const float* adj    = (const float*)d_in[1];
    const float* h0     = (const float*)d_in[2];
    const float* encW   = (const float*)d_in[3];
    const float* encB   = (const float*)d_in[4];
    const float* Wfh    = (const float*)d_in[5];
    const float* Wfu    = (const float*)d_in[6];
    const float* bf     = (const float*)d_in[7];
    const float* Wgh    = (const float*)d_in[8];
    const float* Wgu    = (const float*)d_in[9];
    const float* bg     = (const float*)d_in[10];
    const float* Wch    = (const float*)d_in[11];
    const float* Wcu    = (const float*)d_in[12];
    const float* bc     = (const float*)d_in[13];
    const float* dW1    = (const float*)d_in[14];
    const float* db1    = (const float*)d_in[15];
    const float* dW2    = (const float*)d_in[16];
    const float* db2    = (const float*)d_in[17];
    const float* dW3    = (const float*)d_in[18];
    const float* db3    = (const float*)d_in[19];
    const float* osc    = (const float*)d_in[20];
    const float* obi    = (const float*)d_in[21];
    float* out = (float*)d_out;

    const int smem1 = 45568 * 4;   // 182272 B
    const int smem2 = 57856 * 4;   // 231424 B
    cudaFuncSetAttribute(phase1_kernel, cudaFuncAttributeMaxDynamicSharedMemorySize, smem1);
    cudaFuncSetAttribute(phase2_kernel, cudaFuncAttributeMaxDynamicSharedMemorySize, smem2);

    phase1_kernel<<<NB * NT, 256, smem1>>>(frames, adj, encW, encB,
                                           Wfu, Wgu, Wcu, bf, bg, bc);
    phase2_kernel<<<NB, 256, smem2>>>(adj, h0, Wfh, Wgh, Wch,
                                      dW1, db1, dW2, db2, dW3, db3,
                                      osc, obi, out);
}

// round 4
// speedup vs baseline: 1.7657x; 1.7657x over previous
#include <cuda_runtime.h>
#include <math.h>

#define NB 64
#define NT 128
#define NN 64     // nodes
#define NC 128    // channels
#define NH 64     // hidden
#define NE 192    // 3 gates * 64
#define TP 68     // padded pitch for transposed 64-wide tiles
#define PM 34     // pitch for half-width (32) adjacency tiles

// Precomputed input-path gate contributions U[b,t,n,e] (biases included). 384 MiB.
static __device__ float g_U[(size_t)NB * NT * NN * NE];
// Pooled hidden means per (b,t), consumed by phase 3 decoder. 2 MiB.
static __device__ float g_pool[(size_t)NB * NT * NH];

__device__ __forceinline__ unsigned smem_u32(const void* p) {
    unsigned r;
    asm("{ .reg .u64 t; cvta.to.shared.u64 t, %1; cvt.u32.u64 %0, t; }" : "=r"(r) : "l"(p));
    return r;
}
__device__ __forceinline__ unsigned cluster_rank() {
    unsigned r; asm("mov.u32 %0, %%cluster_ctarank;" : "=r"(r)); return r;
}
__device__ __forceinline__ void st_peer_f2(unsigned laddr, unsigned peer, float a, float b) {
    unsigned raddr;
    asm volatile("mapa.shared::cluster.u32 %0, %1, %2;" : "=r"(raddr) : "r"(laddr), "r"(peer));
    asm volatile("st.shared::cluster.v2.f32 [%0], {%1, %2};" :: "r"(raddr), "f"(a), "f"(b) : "memory");
}
#define CLUSTER_SYNC() do { \
    asm volatile("barrier.cluster.arrive.aligned;" ::: "memory"); \
    asm volatile("barrier.cluster.wait.aligned;" ::: "memory"); } while (0)

__device__ __forceinline__ float rcp_ap(float x) {
    float y; asm("rcp.approx.f32 %0, %1;" : "=f"(y) : "f"(x)); return y;
}
__device__ __forceinline__ float tanh_fast(float x) {
    // (e^{2x}-1)/(e^{2x}+1) = 1 - 2/(e^{2x}+1); robust at +-inf
    return 1.0f - 2.0f * rcp_ap(1.0f + __expf(2.0f * x));
}
__device__ __forceinline__ float sig_fast(float x) {
    return rcp_ap(1.0f + __expf(-x));
}

// ---------------------------------------------------------------------------
// Full-width 64x64 matmul used by phase 1:
// outT[d][n] = sum_m PT[d][m] * AT[m][n]  (i.e. out = A @ P, transposed, pitch TP)
// ---------------------------------------------------------------------------
__device__ __forceinline__ void mmT64(float* __restrict__ outT,
                                      const float* __restrict__ PT,
                                      const float* __restrict__ AT,
                                      int tid)
{
    const int n0 = (tid & 15) * 4;
    const int d0 = (tid >> 4) * 4;
    float acc[4][4];
#pragma unroll
    for (int i = 0; i < 4; i++)
#pragma unroll
        for (int j = 0; j < 4; j++) acc[i][j] = 0.f;

#pragma unroll 4
    for (int m = 0; m < 64; m++) {
        float4 a4 = *(const float4*)&AT[m * TP + n0];
        float av[4] = {a4.x, a4.y, a4.z, a4.w};
        float p[4];
#pragma unroll
        for (int i = 0; i < 4; i++) p[i] = PT[(d0 + i) * TP + m];
#pragma unroll
        for (int i = 0; i < 4; i++)
#pragma unroll
            for (int j = 0; j < 4; j++) acc[i][j] += p[i] * av[j];
    }
#pragma unroll
    for (int i = 0; i < 4; i++)
        *(float4*)&outT[(d0 + i) * TP + n0] =
            make_float4(acc[i][0], acc[i][1], acc[i][2], acc[i][3]);
}

// ---------------------------------------------------------------------------
// Phase 1: per (b,t) tile. grid = 8192, block = 256.  (unchanged from R1)
// ---------------------------------------------------------------------------
__global__ void __launch_bounds__(256, 1) phase1_kernel(
    const float* __restrict__ frames, const float* __restrict__ adj,
    const float* __restrict__ encW, const float* __restrict__ encB,
    const float* __restrict__ Wfu, const float* __restrict__ Wgu, const float* __restrict__ Wcu,
    const float* __restrict__ bf, const float* __restrict__ bg, const float* __restrict__ bc)
{
    extern __shared__ float sm[];
    float* sStage = sm;                 // 16384: [sFr 8192 | sEW 8192], later sWu 12288
    float* sAT = sm + 16384;            // 4352
    float* sXT = sAT + 4352;            // 4352
    float* sYT = sXT + 4352;            // 4352
    float* sZT = sYT + 4352;            // 4352

    const int tid = threadIdx.x;
    const int bt = blockIdx.x;
    const float* fr = frames + (size_t)bt * (NC * NN);
    const float* Ap = adj + (size_t)bt * (NN * NN);

    for (int i = tid; i < NN * NN; i += 256)
        sAT[(i & 63) * TP + (i >> 6)] = Ap[i];
    float* sFr = sStage;
    float* sEW = sStage + 8192;
    for (int i = tid; i < (NC * NN) / 4; i += 256)
        ((float4*)sFr)[i] = ((const float4*)fr)[i];
    for (int i = tid; i < (NC * NH) / 4; i += 256)
        ((float4*)sEW)[i] = ((const float4*)encW)[i];
    __syncthreads();

    const int n0 = (tid & 15) * 4;
    const int d0 = (tid >> 4) * 4;

    // Encode: xT[d][n] = sum_c encW[c][d] * fr[c][n] + encB[d]
    {
        float acc[4][4];
#pragma unroll
        for (int i = 0; i < 4; i++)
#pragma unroll
            for (int j = 0; j < 4; j++) acc[i][j] = 0.f;
#pragma unroll 4
        for (int c = 0; c < NC; c++) {
            float4 a4 = *(const float4*)&sFr[c * 64 + n0];
            float4 w4 = *(const float4*)&sEW[c * 64 + d0];
            float av[4] = {a4.x, a4.y, a4.z, a4.w};
            float wv[4] = {w4.x, w4.y, w4.z, w4.w};
#pragma unroll
            for (int i = 0; i < 4; i++)
#pragma unroll
                for (int j = 0; j < 4; j++) acc[i][j] += wv[i] * av[j];
        }
        float4 b4 = *(const float4*)&encB[d0];
        float bv[4] = {b4.x, b4.y, b4.z, b4.w};
#pragma unroll
        for (int i = 0; i < 4; i++)
            *(float4*)&sXT[(d0 + i) * TP + n0] =
                make_float4(acc[i][0] + bv[i], acc[i][1] + bv[i],
                            acc[i][2] + bv[i], acc[i][3] + bv[i]);
    }
    __syncthreads();
    mmT64(sYT, sXT, sAT, tid);
    __syncthreads();
    mmT64(sZT, sYT, sAT, tid);
    __syncthreads();

    float accf[4][4], accg[4][4], accc[4][4];
    {
        float4 vf = *(const float4*)&bf[d0];
        float4 vg = *(const float4*)&bg[d0];
        float4 vc = *(const float4*)&bc[d0];
        float fv[4] = {vf.x, vf.y, vf.z, vf.w};
        float gv[4] = {vg.x, vg.y, vg.z, vg.w};
        float cv[4] = {vc.x, vc.y, vc.z, vc.w};
#pragma unroll
        for (int i = 0; i < 4; i++)
#pragma unroll
            for (int j = 0; j < 4; j++) {
                accf[i][j] = fv[i]; accg[i][j] = gv[i]; accc[i][j] = cv[i];
            }
    }
    float* sWu = sStage;
#pragma unroll 1
    for (int k = 0; k < 3; k++) {
        __syncthreads();
        for (int i = tid; i < 4096; i += 256) {
            int dd = i >> 6, e = i & 63;
            sWu[dd * NE + e]       = Wfu[k * 4096 + i];
            sWu[dd * NE + 64 + e]  = Wgu[k * 4096 + i];
            sWu[dd * NE + 128 + e] = Wcu[k * 4096 + i];
        }
        __syncthreads();
        const float* src = (k == 0) ? sXT : ((k == 1) ? sYT : sZT);
#pragma unroll 2
        for (int m = 0; m < 64; m++) {
            float4 x4 = *(const float4*)&src[m * TP + n0];
            float xv[4] = {x4.x, x4.y, x4.z, x4.w};
            float4 wf4 = *(const float4*)&sWu[m * NE + d0];
            float4 wg4 = *(const float4*)&sWu[m * NE + 64 + d0];
            float4 wc4 = *(const float4*)&sWu[m * NE + 128 + d0];
            float wf[4] = {wf4.x, wf4.y, wf4.z, wf4.w};
            float wg[4] = {wg4.x, wg4.y, wg4.z, wg4.w};
            float wc[4] = {wc4.x, wc4.y, wc4.z, wc4.w};
#pragma unroll
            for (int i = 0; i < 4; i++)
#pragma unroll
                for (int j = 0; j < 4; j++) {
                    accf[i][j] += wf[i] * xv[j];
                    accg[i][j] += wg[i] * xv[j];
                    accc[i][j] += wc[i] * xv[j];
                }
        }
    }
    float* Ub = g_U + (size_t)bt * (NN * NE);
#pragma unroll
    for (int j = 0; j < 4; j++) {
        int row = (n0 + j) * NE;
        *(float4*)&Ub[row + d0]       = make_float4(accf[0][j], accf[1][j], accf[2][j], accf[3][j]);
        *(float4*)&Ub[row + 64 + d0]  = make_float4(accg[0][j], accg[1][j], accg[2][j], accg[3][j]);
        *(float4*)&Ub[row + 128 + d0] = make_float4(accc[0][j], accc[1][j], accc[2][j], accc[3][j]);
    }
}

// ---------------------------------------------------------------------------
// Phase 2: persistent recurrence, 2-CTA cluster per batch (n-split).
// grid = 128 (64 clusters), block = 256.
// ---------------------------------------------------------------------------
__device__ __forceinline__ void gate_hop(float af[4][2], float ag[4][2], float ac[4][2],
                                         const float* __restrict__ xT,
                                         const float* __restrict__ wb,
                                         int ng0, int e0)
{
#pragma unroll 2
    for (int m = 0; m < 64; m++) {
        float2 x  = *(const float2*)&xT[m * TP + ng0];
        float4 f4 = *(const float4*)&wb[m * NE + e0];
        float4 g4 = *(const float4*)&wb[m * NE + 64 + e0];
        float4 c4 = *(const float4*)&wb[m * NE + 128 + e0];
        float fv[4] = {f4.x, f4.y, f4.z, f4.w};
        float gv[4] = {g4.x, g4.y, g4.z, g4.w};
        float cv[4] = {c4.x, c4.y, c4.z, c4.w};
        float xv[2] = {x.x, x.y};
#pragma unroll
        for (int i = 0; i < 4; i++)
#pragma unroll
            for (int j = 0; j < 2; j++) {
                af[i][j] += fv[i] * xv[j];
                ag[i][j] += gv[i] * xv[j];
                ac[i][j] += cv[i] * xv[j];
            }
    }
}

// Half-width mm: out(4d x 2n in regs) = A_own @ P_full; PT full [d][m] pitch TP,
// AT own-half [m][nloc] pitch PM.
__device__ __forceinline__ void mm_half(float acc[4][2],
                                        const float* __restrict__ PT,
                                        const float* __restrict__ AT,
                                        int d0, int nl0)
{
#pragma unroll
    for (int i = 0; i < 4; i++) { acc[i][0] = 0.f; acc[i][1] = 0.f; }
#pragma unroll 4
    for (int m = 0; m < 64; m++) {
        float2 a2 = *(const float2*)&AT[m * PM + nl0];
        float p[4];
#pragma unroll
        for (int i = 0; i < 4; i++) p[i] = PT[(d0 + i) * TP + m];
#pragma unroll
        for (int i = 0; i < 4; i++) {
            acc[i][0] += p[i] * a2.x;
            acc[i][1] += p[i] * a2.y;
        }
    }
}

__global__ void __launch_bounds__(256, 1) __cluster_dims__(2, 1, 1) phase2_kernel(
    const float* __restrict__ adj, const float* __restrict__ h0,
    const float* __restrict__ Wfh, const float* __restrict__ Wgh, const float* __restrict__ Wch,
    float* __restrict__ out)
{
    extern __shared__ float sm[];
    float* sWh  = sm;                 // 36864
    float* sAT  = sm + 36864;         // 64 x PM = 2176 (own n-half)
    float* sHT  = sm + 39040;         // 4352 (full width)
    float* sH1T = sm + 43392;         // 4352 (full width, exchanged)
    float* sH2T = sm + 47744;         // 4352 (own half valid only)

    const int tid = threadIdx.x;
    const int b = blockIdx.x >> 1;
    const unsigned rank = cluster_rank();
    const unsigned peer = rank ^ 1u;
    const int halfbase = (int)rank * 32;

    // Stage hidden-path weights
    for (int i = tid; i < 3 * 4096; i += 256) {
        int k = i >> 12; int r = i & 4095; int m = r >> 6; int e = r & 63;
        sWh[(k * 64 + m) * NE + e]       = Wfh[i];
        sWh[(k * 64 + m) * NE + 64 + e]  = Wgh[i];
        sWh[(k * 64 + m) * NE + 128 + e] = Wch[i];
    }
    // h0 full, transposed
    for (int i = tid; i < 4096; i += 256)
        sHT[(i & 63) * TP + (i >> 6)] = h0[b * 4096 + i];
    __syncthreads();
    CLUSTER_SYNC();

    const unsigned u_sHT  = smem_u32(sHT);
    const unsigned u_sH1T = smem_u32(sH1T);

    const int nl0 = (tid & 15) * 2;        // local n (0..30)
    const int ng0 = halfbase + nl0;        // global n
    const int e0  = (tid >> 4) * 4;        // e/d tile base (0..60)

    for (int t = 0; t < NT; t++) {
        // Stage own-half adjacency: AT[m][nloc] = A[halfbase+nloc][m]
        const float* Ap = adj + ((size_t)(b * NT + t)) * 4096 + (size_t)halfbase * 64;
        for (int i = tid; i < 2048; i += 256) {
            int nl = i >> 6, m = i & 63;
            sAT[m * PM + nl] = Ap[nl * 64 + m];
        }
        // Init gate accs from U (own n rows)
        float af[4][2], ag[4][2], ac[4][2];
        {
            const float* Ub = g_U + ((size_t)(b * NT + t)) * (NN * NE);
#pragma unroll
            for (int j = 0; j < 2; j++) {
                int row = (ng0 + j) * NE;
                float4 uf = *(const float4*)&Ub[row + e0];
                float4 ug = *(const float4*)&Ub[row + 64 + e0];
                float4 uc = *(const float4*)&Ub[row + 128 + e0];
                af[0][j] = uf.x; af[1][j] = uf.y; af[2][j] = uf.z; af[3][j] = uf.w;
                ag[0][j] = ug.x; ag[1][j] = ug.y; ag[2][j] = ug.z; ag[3][j] = ug.w;
                ac[0][j] = uc.x; ac[1][j] = uc.y; ac[2][j] = uc.z; ac[3][j] = uc.w;
            }
        }
        __syncthreads();

        // hop 0 (x = h, own cols) + h1 = A h (own rows)
        gate_hop(af, ag, ac, sHT, sWh, ng0, e0);
        float mmv[4][2];
        mm_half(mmv, sHT, sAT, e0, nl0);
        // write h1 own-half: local + peer
#pragma unroll
        for (int i = 0; i < 4; i++) {
            int off = (e0 + i) * TP + ng0;
            *(float2*)&sH1T[off] = make_float2(mmv[i][0], mmv[i][1]);
            st_peer_f2(u_sH1T + (unsigned)off * 4u, peer, mmv[i][0], mmv[i][1]);
        }
        CLUSTER_SYNC();   // h1 full everywhere

        // hop 1 (x = h1) + h2 = A h1 (own rows, local only)
        gate_hop(af, ag, ac, sH1T, sWh + 64 * NE, ng0, e0);
        mm_half(mmv, sH1T, sAT, e0, nl0);
#pragma unroll
        for (int i = 0; i < 4; i++)
            *(float2*)&sH2T[(e0 + i) * TP + ng0] = make_float2(mmv[i][0], mmv[i][1]);
        __syncthreads();

        // hop 2 (x = h2, own cols)
        gate_hop(af, ag, ac, sH2T, sWh + 128 * NE, ng0, e0);

        // Nonlinearity -> h_new own tile; write local + peer
#pragma unroll
        for (int i = 0; i < 4; i++) {
            float h0v, h1v;
            {
                float f = sig_fast(af[i][0]);
                float tg = tanh_fast(ag[i][0]);
                float tc = tanh_fast(ac[i][0]);
                h0v = f * (tg - tc) + tc;
            }
            {
                float f = sig_fast(af[i][1]);
                float tg = tanh_fast(ag[i][1]);
                float tc = tanh_fast(ac[i][1]);
                h1v = f * (tg - tc) + tc;
            }
            int off = (e0 + i) * TP + ng0;
            *(float2*)&sHT[off] = make_float2(h0v, h1v);
            st_peer_f2(u_sHT + (unsigned)off * 4u, peer, h0v, h1v);
        }
        CLUSTER_SYNC();   // h_new full everywhere

        // Pooled mean (rank 0): pooled[d] = mean_n sHT[d][n]
        if (rank == 0) {
            int d = tid >> 2, q = tid & 3;
            float s = 0.f;
            const float* row = &sHT[d * TP + q * 16];
#pragma unroll
            for (int nn = 0; nn < 16; nn++) s += row[nn];
            s += __shfl_xor_sync(0xFFFFFFFFu, s, 1);
            s += __shfl_xor_sync(0xFFFFFFFFu, s, 2);
            if (q == 0)
                g_pool[((size_t)(b * NT + t)) * NH + d] = s * (1.0f / 64.0f);
        }
        __syncthreads();
    }

    // final_hidden[b,0,n,d] at out offset NB*NT*6 (rank 0 writes full)
    if (rank == 0) {
        float* fh = out + (size_t)NB * NT * 6 + (size_t)b * (NN * NH);
        for (int i = tid; i < 4096; i += 256)
            fh[i] = sHT[(i & 63) * TP + (i >> 6)];
    }
    CLUSTER_SYNC();   // no CTA exits while peer may still target its smem
}

// ---------------------------------------------------------------------------
// Phase 3: decoder MLP per (b,t). grid = 8192, block = 128.
// ---------------------------------------------------------------------------
__global__ void __launch_bounds__(128, 8) phase3_kernel(
    const float* __restrict__ dW1, const float* __restrict__ db1,
    const float* __restrict__ dW2, const float* __restrict__ db2,
    const float* __restrict__ dW3, const float* __restrict__ db3,
    const float* __restrict__ osc, const float* __restrict__ obi,
    float* __restrict__ out)
{
    __shared__ float sp[64];
    __shared__ float z1[128];
    __shared__ float z2[64];
    const int bt = blockIdx.x;
    const int tid = threadIdx.x;

    if (tid < 64) sp[tid] = g_pool[(size_t)bt * NH + tid];
    __syncthreads();
    {
        float a = db1[tid];
#pragma unroll 4
        for (int d = 0; d < 64; d++) a += sp[d] * dW1[d * 128 + tid];
        z1[tid] = fmaxf(a, 0.f);
    }
    __syncthreads();
    if (tid < 64) {
        float a = db2[tid];
#pragma unroll 4
        for (int i = 0; i < 128; i++) a += z1[i] * dW2[i * 64 + tid];
        z2[tid] = fmaxf(a, 0.f);
    }
    __syncthreads();
    if (tid < 6) {
        float a = db3[tid];
#pragma unroll 4
        for (int j = 0; j < 64; j++) a += z2[j] * dW3[j * 6 + tid];
        out[(size_t)bt * 6 + tid] = a * osc[tid] + obi[tid];
    }
}

extern "C" void kernel_launch(void* const* d_in, const int* in_sizes, int n_in,
                              void* d_out, int out_size) {
    const float* frames = (const float*)d_in[0];
    const float* adj    = (const float*)d_in[1];
    const float* h0     = (const float*)d_in[2];
    const float* encW   = (const float*)d_in[3];
    const float* encB   = (const float*)d_in[4];
    const float* Wfh    = (const float*)d_in[5];
    const float* Wfu    = (const float*)d_in[6];
    const float* bf     = (const float*)d_in[7];
    const float* Wgh    = (const float*)d_in[8];
    const float* Wgu    = (const float*)d_in[9];
    const float* bg     = (const float*)d_in[10];
    const float* Wch    = (const float*)d_in[11];
    const float* Wcu    = (const float*)d_in[12];
    const float* bc     = (const float*)d_in[13];
    const float* dW1    = (const float*)d_in[14];
    const float* db1    = (const float*)d_in[15];
    const float* dW2    = (const float*)d_in[16];
    const float* db2    = (const float*)d_in[17];
    const float* dW3    = (const float*)d_in[18];
    const float* db3    = (const float*)d_in[19];
    const float* osc    = (const float*)d_in[20];
    const float* obi    = (const float*)d_in[21];
    float* out = (float*)d_out;

    const int smem1 = 38144 * 4;   // 152576 B
    const int smem2 = 52096 * 4;   // 208384 B
    cudaFuncSetAttribute(phase1_kernel, cudaFuncAttributeMaxDynamicSharedMemorySize, smem1);
    cudaFuncSetAttribute(phase2_kernel, cudaFuncAttributeMaxDynamicSharedMemorySize, smem2);

    phase1_kernel<<<NB * NT, 256, smem1>>>(frames, adj, encW, encB,
                                           Wfu, Wgu, Wcu, bf, bg, bc);
    phase2_kernel<<<NB * 2, 256, smem2>>>(adj, h0, Wfh, Wgh, Wch, out);
    phase3_kernel<<<NB * NT, 128>>>(dW1, db1, dW2, db2, dW3, db3, osc, obi, out);
}

// round 5
// speedup vs baseline: 1.8982x; 1.0751x over previous
#include <cuda_runtime.h>
#include <math.h>

#define NB 64
#define NT 128
#define NN 64     // nodes
#define NC 128    // channels
#define NH 64     // hidden
#define NE 192    // 3 gates * 64
#define TP 68     // padded pitch for transposed 64-wide tiles
#define PM 34     // pitch for half-width (32) adjacency tiles

// Precomputed input-path gate contributions U[b,t,n,e] (biases included). 384 MiB.
static __device__ float g_U[(size_t)NB * NT * NN * NE];
// Pooled hidden means per (b,t), consumed by phase 3 decoder. 2 MiB.
static __device__ float g_pool[(size_t)NB * NT * NH];

__device__ __forceinline__ unsigned smem_u32(const void* p) {
    unsigned r;
    asm("{ .reg .u64 t; cvta.to.shared.u64 t, %1; cvt.u32.u64 %0, t; }" : "=r"(r) : "l"(p));
    return r;
}
__device__ __forceinline__ unsigned cluster_rank() {
    unsigned r; asm("mov.u32 %0, %%cluster_ctarank;" : "=r"(r)); return r;
}
__device__ __forceinline__ void st_peer_f2(unsigned laddr, unsigned peer, float a, float b) {
    unsigned raddr;
    asm volatile("mapa.shared::cluster.u32 %0, %1, %2;" : "=r"(raddr) : "r"(laddr), "r"(peer));
    asm volatile("st.shared::cluster.v2.f32 [%0], {%1, %2};" :: "r"(raddr), "f"(a), "f"(b) : "memory");
}
#define CLUSTER_SYNC() do { \
    asm volatile("barrier.cluster.arrive.aligned;" ::: "memory"); \
    asm volatile("barrier.cluster.wait.aligned;" ::: "memory"); } while (0)

__device__ __forceinline__ float rcp_ap(float x) {
    float y; asm("rcp.approx.f32 %0, %1;" : "=f"(y) : "f"(x)); return y;
}
__device__ __forceinline__ float tanh_fast(float x) {
    return 1.0f - 2.0f * rcp_ap(1.0f + __expf(2.0f * x));
}
__device__ __forceinline__ float sig_fast(float x) {
    return rcp_ap(1.0f + __expf(-x));
}

// ---------------------------------------------------------------------------
// Full-width 64x64 matmul (phase 1):
// outT[d][n] = sum_m PT[d][m] * AT[m][n]  (out = A @ P, transposed, pitch TP)
// ---------------------------------------------------------------------------
__device__ __forceinline__ void mmT64(float* __restrict__ outT,
                                      const float* __restrict__ PT,
                                      const float* __restrict__ AT,
                                      int tid)
{
    const int n0 = (tid & 15) * 4;
    const int d0 = (tid >> 4) * 4;
    float acc[4][4];
#pragma unroll
    for (int i = 0; i < 4; i++)
#pragma unroll
        for (int j = 0; j < 4; j++) acc[i][j] = 0.f;

#pragma unroll 4
    for (int m = 0; m < 64; m++) {
        float4 a4 = *(const float4*)&AT[m * TP + n0];
        float av[4] = {a4.x, a4.y, a4.z, a4.w};
        float p[4];
#pragma unroll
        for (int i = 0; i < 4; i++) p[i] = PT[(d0 + i) * TP + m];
#pragma unroll
        for (int i = 0; i < 4; i++)
#pragma unroll
            for (int j = 0; j < 4; j++) acc[i][j] += p[i] * av[j];
    }
#pragma unroll
    for (int i = 0; i < 4; i++)
        *(float4*)&outT[(d0 + i) * TP + n0] =
            make_float4(acc[i][0], acc[i][1], acc[i][2], acc[i][3]);
}

// ---------------------------------------------------------------------------
// Phase 1: per (b,t) tile. grid = 8192, block = 256.
// smem = 69632 B (sAT/sXT/sYT/sZT only) -> 2-3 CTAs/SM.
// Weights + frames read straight from gmem (L2-broadcast across CTAs).
// ---------------------------------------------------------------------------
__global__ void __launch_bounds__(256, 2) phase1_kernel(
    const float* __restrict__ frames, const float* __restrict__ adj,
    const float* __restrict__ encW, const float* __restrict__ encB,
    const float* __restrict__ Wfu, const float* __restrict__ Wgu, const float* __restrict__ Wcu,
    const float* __restrict__ bf, const float* __restrict__ bg, const float* __restrict__ bc)
{
    extern __shared__ float sm[];
    float* sAT = sm;               // 4352
    float* sXT = sm + 4352;        // 4352
    float* sYT = sm + 8704;        // 4352
    float* sZT = sm + 13056;       // 4352

    const int tid = threadIdx.x;
    const int bt = blockIdx.x;
    const float* fr = frames + (size_t)bt * (NC * NN);
    const float* Ap = adj + (size_t)bt * (NN * NN);

    for (int i = tid; i < NN * NN; i += 256)
        sAT[(i & 63) * TP + (i >> 6)] = Ap[i];
    __syncthreads();

    const int n0 = (tid & 15) * 4;
    const int d0 = (tid >> 4) * 4;

    // Encode: xT[d][n] = sum_c encW[c][d] * fr[c][n] + encB[d]   (gmem operands)
    {
        float acc[4][4];
#pragma unroll
        for (int i = 0; i < 4; i++)
#pragma unroll
            for (int j = 0; j < 4; j++) acc[i][j] = 0.f;
#pragma unroll 4
        for (int c = 0; c < NC; c++) {
            float4 a4 = __ldg((const float4*)&fr[c * 64 + n0]);
            float4 w4 = __ldg((const float4*)&encW[c * 64 + d0]);
            float av[4] = {a4.x, a4.y, a4.z, a4.w};
            float wv[4] = {w4.x, w4.y, w4.z, w4.w};
#pragma unroll
            for (int i = 0; i < 4; i++)
#pragma unroll
                for (int j = 0; j < 4; j++) acc[i][j] += wv[i] * av[j];
        }
        float4 b4 = __ldg((const float4*)&encB[d0]);
        float bv[4] = {b4.x, b4.y, b4.z, b4.w};
#pragma unroll
        for (int i = 0; i < 4; i++)
            *(float4*)&sXT[(d0 + i) * TP + n0] =
                make_float4(acc[i][0] + bv[i], acc[i][1] + bv[i],
                            acc[i][2] + bv[i], acc[i][3] + bv[i]);
    }
    __syncthreads();
    mmT64(sYT, sXT, sAT, tid);
    __syncthreads();
    mmT64(sZT, sYT, sAT, tid);
    __syncthreads();

    // Gates: U = bias + sum_k y_k @ Wu_k   (weights streamed from gmem/L2)
    float accf[4][4], accg[4][4], accc[4][4];
    {
        float4 vf = __ldg((const float4*)&bf[d0]);
        float4 vg = __ldg((const float4*)&bg[d0]);
        float4 vc = __ldg((const float4*)&bc[d0]);
        float fv[4] = {vf.x, vf.y, vf.z, vf.w};
        float gv[4] = {vg.x, vg.y, vg.z, vg.w};
        float cv[4] = {vc.x, vc.y, vc.z, vc.w};
#pragma unroll
        for (int i = 0; i < 4; i++)
#pragma unroll
            for (int j = 0; j < 4; j++) {
                accf[i][j] = fv[i]; accg[i][j] = gv[i]; accc[i][j] = cv[i];
            }
    }
#pragma unroll 1
    for (int k = 0; k < 3; k++) {
        const float* src = (k == 0) ? sXT : ((k == 1) ? sYT : sZT);
        const float* Wf = Wfu + k * 4096;
        const float* Wg = Wgu + k * 4096;
        const float* Wc = Wcu + k * 4096;
#pragma unroll 4
        for (int m = 0; m < 64; m++) {
            float4 x4 = *(const float4*)&src[m * TP + n0];
            float xv[4] = {x4.x, x4.y, x4.z, x4.w};
            float4 wf4 = __ldg((const float4*)&Wf[m * 64 + d0]);
            float4 wg4 = __ldg((const float4*)&Wg[m * 64 + d0]);
            float4 wc4 = __ldg((const float4*)&Wc[m * 64 + d0]);
            float wf[4] = {wf4.x, wf4.y, wf4.z, wf4.w};
            float wg[4] = {wg4.x, wg4.y, wg4.z, wg4.w};
            float wc[4] = {wc4.x, wc4.y, wc4.z, wc4.w};
#pragma unroll
            for (int i = 0; i < 4; i++)
#pragma unroll
                for (int j = 0; j < 4; j++) {
                    accf[i][j] += wf[i] * xv[j];
                    accg[i][j] += wg[i] * xv[j];
                    accc[i][j] += wc[i] * xv[j];
                }
        }
    }
    float* Ub = g_U + (size_t)bt * (NN * NE);
#pragma unroll
    for (int j = 0; j < 4; j++) {
        int row = (n0 + j) * NE;
        *(float4*)&Ub[row + d0]       = make_float4(accf[0][j], accf[1][j], accf[2][j], accf[3][j]);
        *(float4*)&Ub[row + 64 + d0]  = make_float4(accg[0][j], accg[1][j], accg[2][j], accg[3][j]);
        *(float4*)&Ub[row + 128 + d0] = make_float4(accc[0][j], accc[1][j], accc[2][j], accc[3][j]);
    }
}

// ---------------------------------------------------------------------------
// Phase 2: persistent recurrence, 2-CTA cluster per batch (n-split).
// grid = 128 (64 clusters), block = 512 (16 warps for latency hiding).
// ---------------------------------------------------------------------------
__device__ __forceinline__ void gate_hop512(float af[2][2], float ag[2][2], float ac[2][2],
                                            const float* __restrict__ xT,
                                            const float* __restrict__ wb,
                                            int ng0, int e0)
{
#pragma unroll 4
    for (int m = 0; m < 64; m++) {
        float2 x  = *(const float2*)&xT[m * TP + ng0];
        float2 f2 = *(const float2*)&wb[m * NE + e0];
        float2 g2 = *(const float2*)&wb[m * NE + 64 + e0];
        float2 c2 = *(const float2*)&wb[m * NE + 128 + e0];
        af[0][0] += f2.x * x.x;  af[0][1] += f2.x * x.y;
        af[1][0] += f2.y * x.x;  af[1][1] += f2.y * x.y;
        ag[0][0] += g2.x * x.x;  ag[0][1] += g2.x * x.y;
        ag[1][0] += g2.y * x.x;  ag[1][1] += g2.y * x.y;
        ac[0][0] += c2.x * x.x;  ac[0][1] += c2.x * x.y;
        ac[1][0] += c2.y * x.x;  ac[1][1] += c2.y * x.y;
    }
}

// Half mm: out(2d x 2n) = A_own @ P_full
__device__ __forceinline__ void mm_half512(float acc[2][2],
                                           const float* __restrict__ PT,
                                           const float* __restrict__ AT,
                                           int d0, int nl0)
{
    acc[0][0] = acc[0][1] = acc[1][0] = acc[1][1] = 0.f;
#pragma unroll 4
    for (int m = 0; m < 64; m++) {
        float2 a2 = *(const float2*)&AT[m * PM + nl0];
        float p0 = PT[d0 * TP + m];
        float p1 = PT[(d0 + 1) * TP + m];
        acc[0][0] += p0 * a2.x;  acc[0][1] += p0 * a2.y;
        acc[1][0] += p1 * a2.x;  acc[1][1] += p1 * a2.y;
    }
}

__global__ void __launch_bounds__(512, 1) __cluster_dims__(2, 1, 1) phase2_kernel(
    const float* __restrict__ adj, const float* __restrict__ h0,
    const float* __restrict__ Wfh, const float* __restrict__ Wgh, const float* __restrict__ Wch,
    float* __restrict__ out)
{
    extern __shared__ float sm[];
    float* sWh  = sm;                 // 36864
    float* sAT  = sm + 36864;         // 2176 (own n-half)
    float* sHT  = sm + 39040;         // 4352 (full width)
    float* sH1T = sm + 43392;         // 4352 (full width, exchanged)
    float* sH2T = sm + 47744;         // 4352 (own half valid only)

    const int tid = threadIdx.x;
    const int b = blockIdx.x >> 1;
    const unsigned rank = cluster_rank();
    const unsigned peer = rank ^ 1u;
    const int halfbase = (int)rank * 32;

    for (int i = tid; i < 3 * 4096; i += 512) {
        int k = i >> 12; int r = i & 4095; int m = r >> 6; int e = r & 63;
        sWh[(k * 64 + m) * NE + e]       = Wfh[i];
        sWh[(k * 64 + m) * NE + 64 + e]  = Wgh[i];
        sWh[(k * 64 + m) * NE + 128 + e] = Wch[i];
    }
    for (int i = tid; i < 4096; i += 512)
        sHT[(i & 63) * TP + (i >> 6)] = h0[b * 4096 + i];
    __syncthreads();
    CLUSTER_SYNC();

    const unsigned u_sHT  = smem_u32(sHT);
    const unsigned u_sH1T = smem_u32(sH1T);

    const int nl0 = (tid & 15) * 2;        // local n (0..30)
    const int ng0 = halfbase + nl0;        // global n
    const int e0  = (tid >> 4) * 2;        // e/d tile base (0..62)

    for (int t = 0; t < NT; t++) {
        const float* Ap = adj + ((size_t)(b * NT + t)) * 4096 + (size_t)halfbase * 64;
        for (int i = tid; i < 2048; i += 512) {
            int nl = i >> 6, m = i & 63;
            sAT[m * PM + nl] = Ap[nl * 64 + m];
        }
        float af[2][2], ag[2][2], ac[2][2];
        {
            const float* Ub = g_U + ((size_t)(b * NT + t)) * (NN * NE);
#pragma unroll
            for (int j = 0; j < 2; j++) {
                int row = (ng0 + j) * NE;
                float2 uf = *(const float2*)&Ub[row + e0];
                float2 ug = *(const float2*)&Ub[row + 64 + e0];
                float2 uc = *(const float2*)&Ub[row + 128 + e0];
                af[0][j] = uf.x; af[1][j] = uf.y;
                ag[0][j] = ug.x; ag[1][j] = ug.y;
                ac[0][j] = uc.x; ac[1][j] = uc.y;
            }
        }
        __syncthreads();

        // hop 0 (x = h) + h1 = A h (own rows)
        gate_hop512(af, ag, ac, sHT, sWh, ng0, e0);
        float mmv[2][2];
        mm_half512(mmv, sHT, sAT, e0, nl0);
#pragma unroll
        for (int i = 0; i < 2; i++) {
            int off = (e0 + i) * TP + ng0;
            *(float2*)&sH1T[off] = make_float2(mmv[i][0], mmv[i][1]);
            st_peer_f2(u_sH1T + (unsigned)off * 4u, peer, mmv[i][0], mmv[i][1]);
        }
        CLUSTER_SYNC();   // h1 full everywhere

        // hop 1 (x = h1) + h2 = A h1 (own rows, local only)
        gate_hop512(af, ag, ac, sH1T, sWh + 64 * NE, ng0, e0);
        mm_half512(mmv, sH1T, sAT, e0, nl0);
#pragma unroll
        for (int i = 0; i < 2; i++)
            *(float2*)&sH2T[(e0 + i) * TP + ng0] = make_float2(mmv[i][0], mmv[i][1]);
        __syncthreads();

        // hop 2 (x = h2)
        gate_hop512(af, ag, ac, sH2T, sWh + 128 * NE, ng0, e0);

        // Nonlinearity -> h_new own tile; write local + peer
#pragma unroll
        for (int i = 0; i < 2; i++) {
            float hv0, hv1;
            {
                float f = sig_fast(af[i][0]);
                float tg = tanh_fast(ag[i][0]);
                float tc = tanh_fast(ac[i][0]);
                hv0 = f * (tg - tc) + tc;
            }
            {
                float f = sig_fast(af[i][1]);
                float tg = tanh_fast(ag[i][1]);
                float tc = tanh_fast(ac[i][1]);
                hv1 = f * (tg - tc) + tc;
            }
            int off = (e0 + i) * TP + ng0;
            *(float2*)&sHT[off] = make_float2(hv0, hv1);
            st_peer_f2(u_sHT + (unsigned)off * 4u, peer, hv0, hv1);
        }
        CLUSTER_SYNC();   // h_new full everywhere

        // Pooled mean (rank 0): pooled[d] = mean_n sHT[d][n]
        if (rank == 0) {
            int d = tid >> 3, q = tid & 7;
            float s = 0.f;
            const float* row = &sHT[d * TP + q * 8];
#pragma unroll
            for (int nn = 0; nn < 8; nn++) s += row[nn];
            s += __shfl_xor_sync(0xFFFFFFFFu, s, 1);
            s += __shfl_xor_sync(0xFFFFFFFFu, s, 2);
            s += __shfl_xor_sync(0xFFFFFFFFu, s, 4);
            if (q == 0)
                g_pool[((size_t)(b * NT + t)) * NH + d] = s * (1.0f / 64.0f);
        }
        __syncthreads();
    }

    if (rank == 0) {
        float* fh = out + (size_t)NB * NT * 6 + (size_t)b * (NN * NH);
        for (int i = tid; i < 4096; i += 512)
            fh[i] = sHT[(i & 63) * TP + (i >> 6)];
    }
    CLUSTER_SYNC();   // no CTA exits while peer may still target its smem
}

// ---------------------------------------------------------------------------
// Phase 3: decoder MLP per (b,t). grid = 8192, block = 128.
// ---------------------------------------------------------------------------
__global__ void __launch_bounds__(128, 8) phase3_kernel(
    const float* __restrict__ dW1, const float* __restrict__ db1,
    const float* __restrict__ dW2, const float* __restrict__ db2,
    const float* __restrict__ dW3, const float* __restrict__ db3,
    const float* __restrict__ osc, const float* __restrict__ obi,
    float* __restrict__ out)
{
    __shared__ float sp[64];
    __shared__ float z1[128];
    __shared__ float z2[64];
    const int bt = blockIdx.x;
    const int tid = threadIdx.x;

    if (tid < 64) sp[tid] = g_pool[(size_t)bt * NH + tid];
    __syncthreads();
    {
        float a = db1[tid];
#pragma unroll 4
        for (int d = 0; d < 64; d++) a += sp[d] * dW1[d * 128 + tid];
        z1[tid] = fmaxf(a, 0.f);
    }
    __syncthreads();
    if (tid < 64) {
        float a = db2[tid];
#pragma unroll 4
        for (int i = 0; i < 128; i++) a += z1[i] * dW2[i * 64 + tid];
        z2[tid] = fmaxf(a, 0.f);
    }
    __syncthreads();
    if (tid < 6) {
        float a = db3[tid];
#pragma unroll 4
        for (int j = 0; j < 64; j++) a += z2[j] * dW3[j * 6 + tid];
        out[(size_t)bt * 6 + tid] = a * osc[tid] + obi[tid];
    }
}

extern "C" void kernel_launch(void* const* d_in, const int* in_sizes, int n_in,
                              void* d_out, int out_size) {
    const float* frames = (const float*)d_in[0];
    const float* adj    = (const float*)d_in[1];
    const float* h0     = (const float*)d_in[2];
    const float* encW   = (const float*)d_in[3];
    const float* encB   = (const float*)d_in[4];
    const float* Wfh    = (const float*)d_in[5];
    const float* Wfu    = (const float*)d_in[6];
    const float* bf     = (const float*)d_in[7];
    const float* Wgh    = (const float*)d_in[8];
    const float* Wgu    = (const float*)d_in[9];
    const float* bg     = (const float*)d_in[10];
    const float* Wch    = (const float*)d_in[11];
    const float* Wcu    = (const float*)d_in[12];
    const float* bc     = (const float*)d_in[13];
    const float* dW1    = (const float*)d_in[14];
    const float* db1    = (const float*)d_in[15];
    const float* dW2    = (const float*)d_in[16];
    const float* db2    = (const float*)d_in[17];
    const float* dW3    = (const float*)d_in[18];
    const float* db3    = (const float*)d_in[19];
    const float* osc    = (const float*)d_in[20];
    const float* obi    = (const float*)d_in[21];
    float* out = (float*)d_out;

    const int smem1 = 17408 * 4;   // 69632 B  -> 2-3 CTAs/SM
    const int smem2 = 52096 * 4;   // 208384 B
    cudaFuncSetAttribute(phase1_kernel, cudaFuncAttributeMaxDynamicSharedMemorySize, smem1);
    cudaFuncSetAttribute(phase2_kernel, cudaFuncAttributeMaxDynamicSharedMemorySize, smem2);

    phase1_kernel<<<NB * NT, 256, smem1>>>(frames, adj, encW, encB,
                                           Wfu, Wgu, Wcu, bf, bg, bc);
    phase2_kernel<<<NB * 2, 512, smem2>>>(adj, h0, Wfh, Wgh, Wch, out);
    phase3_kernel<<<NB * NT, 128>>>(dW1, db1, dW2, db2, dW3, db3, osc, obi, out);
}